// round 15
// baseline (speedup 1.0000x reference)
#include <cuda_runtime.h>
#include <cuda_fp16.h>

#define NN      100000
#define EE      1600000
#define INC     165
#define C1      128
#define C2      64

#define G1_BLOCKS   782              // ceil(NN/128) gemm1 tiles
#define HIST_BLOCKS 1563             // ceil(EE/4/256) int4 histogram blocks
#define NB_SCAN     49               // ceil(NN/2048)

// ---------------- scratch (static device globals; no runtime alloc) ----------------
__device__ int    g_cnt[NN];         // zero-init at load; re-zeroed by k_agg2out
__device__ int    g_cur[NN];
__device__ int    g_rowptr[NN + 1];
__device__ int    g_tot[64];         // lookback totals (+1 sentinel); reset by k_agg2out
__device__ float  g_dinv[NN];
__device__ __align__(16) uint2 g_edge[EE];   // .x = src idx, .y = bits(dinv[src])
__device__ __half g_H1h[(size_t)NN * C1];    // raw fp16 X@W1
__device__ __half g_A1h[(size_t)NN * C1];    // relu layer-1 activations (fp16)
__device__ __half g_H2h[(size_t)NN * C2];    // raw fp16 A1@W2

// ---------------- helpers ----------------
__device__ __forceinline__ unsigned h2_as_u(__half2 h) {
    return *reinterpret_cast<unsigned*>(&h);
}

// fp16 MMA (m16n8k16, fp32 accum)
__device__ __forceinline__ void mma_f16(float4& c,
                                        unsigned a0, unsigned a1, unsigned a2, unsigned a3,
                                        unsigned b0, unsigned b1) {
    asm volatile(
        "mma.sync.aligned.m16n8k16.row.col.f32.f16.f16.f32 "
        "{%0,%1,%2,%3}, {%4,%5,%6,%7}, {%8,%9}, {%0,%1,%2,%3};"
        : "+f"(c.x), "+f"(c.y), "+f"(c.z), "+f"(c.w)
        : "r"(a0), "r"(a1), "r"(a2), "r"(a3), "r"(b0), "r"(b1));
}

// ---------------- k_head: gemm1 tiles (blocks < G1_BLOCKS) ∥ int4 histogram --------
__global__ __launch_bounds__(256) void k_head(const float* __restrict__ X,
                                              const float* __restrict__ W,
                                              const int* __restrict__ dst,
                                              int n, int e) {
    if (blockIdx.x >= G1_BLOCKS) {
        int i = (blockIdx.x - G1_BLOCKS) * 256 + threadIdx.x;
        int j = i * 4;
        if (j + 3 < e) {
            int4 d = *(const int4*)(dst + j);
            atomicAdd(&g_cnt[d.x], 1);
            atomicAdd(&g_cnt[d.y], 1);
            atomicAdd(&g_cnt[d.z], 1);
            atomicAdd(&g_cnt[d.w], 1);
        } else {
            for (; j < e; j++) atomicAdd(&g_cnt[dst[j]], 1);
        }
        return;
    }

    __shared__ unsigned As[128 * 20];   // [m][k/2] half2, stride 20 (16 used)
    __shared__ unsigned Bs[16 * 136];   // [k/2][n] half2 of (W[k],W[k+1]), stride 136

    int tid  = threadIdx.x;
    int wid  = tid >> 5;
    int lane = tid & 31;
    int g    = lane >> 2;
    int t    = lane & 3;
    int wm   = (wid & 3) * 32;
    int wn   = (wid >> 2) * 64;
    int rowBase = blockIdx.x * 128;

    float4 C[2][8];
#pragma unroll
    for (int a = 0; a < 2; a++)
#pragma unroll
        for (int b2 = 0; b2 < 8; b2++) C[a][b2] = make_float4(0.f, 0.f, 0.f, 0.f);

    for (int kt = 0; kt < 6; kt++) {        // 6*32 = 192 >= 165
        int k0 = kt * 32;
#pragma unroll
        for (int i = tid; i < 2048; i += 256) {
            int r = i >> 4, ip = i & 15;
            int gr = rowBase + r, gk = k0 + 2 * ip;
            float v0 = (gr < n && gk < INC)     ? X[(size_t)gr * INC + gk]     : 0.f;
            float v1 = (gr < n && gk + 1 < INC) ? X[(size_t)gr * INC + gk + 1] : 0.f;
            As[r * 20 + ip] = h2_as_u(__floats2half2_rn(v0, v1));
        }
#pragma unroll
        for (int i = tid; i < 2048; i += 256) {
            int ii = i >> 7, c = i & 127;
            int gk = k0 + 2 * ii;
            float v0 = (gk < INC)     ? W[(size_t)gk * C1 + c]       : 0.f;
            float v1 = (gk + 1 < INC) ? W[(size_t)(gk + 1) * C1 + c] : 0.f;
            Bs[ii * 136 + c] = h2_as_u(__floats2half2_rn(v0, v1));
        }
        __syncthreads();

#pragma unroll
        for (int ks = 0; ks < 2; ks++) {
            int kb = ks * 8;
            unsigned a[2][4];
#pragma unroll
            for (int mg = 0; mg < 2; mg++) {
                int r = wm + mg * 16 + g;
                a[mg][0] = As[r * 20 + kb + t];
                a[mg][1] = As[(r + 8) * 20 + kb + t];
                a[mg][2] = As[r * 20 + kb + t + 4];
                a[mg][3] = As[(r + 8) * 20 + kb + t + 4];
            }
#pragma unroll
            for (int nc = 0; nc < 8; nc++) {
                int cb = wn + nc * 8 + g;
                unsigned b0 = Bs[(kb + t) * 136 + cb];
                unsigned b1 = Bs[(kb + t + 4) * 136 + cb];
                mma_f16(C[0][nc], a[0][0], a[0][1], a[0][2], a[0][3], b0, b1);
                mma_f16(C[1][nc], a[1][0], a[1][1], a[1][2], a[1][3], b0, b1);
            }
        }
        __syncthreads();
    }

#pragma unroll
    for (int mg = 0; mg < 2; mg++) {
        int r = rowBase + wm + mg * 16 + g;
#pragma unroll
        for (int nc = 0; nc < 8; nc++) {
            int c = wn + nc * 8 + 2 * t;
            if (r < n)
                *(__half2*)&g_H1h[(size_t)r * C1 + c] =
                    __floats2half2_rn(C[mg][nc].x, C[mg][nc].y);
            if (r + 8 < n)
                *(__half2*)&g_H1h[(size_t)(r + 8) * C1 + c] =
                    __floats2half2_rn(C[mg][nc].z, C[mg][nc].w);
        }
    }
}

// ---------------- scan: fused block scan + parallel lookback + finalize ------------
__global__ void k_scan(int n, int e) {
    __shared__ int s[512];
    __shared__ int sprefix;
    int tid  = threadIdx.x;
    int b    = blockIdx.x;
    int base = b * 2048 + tid * 4;

    int v[4];
    int local = 0;
#pragma unroll
    for (int i = 0; i < 4; i++) {
        int idx = base + i;
        int t = (idx < n) ? g_cnt[idx] : 0;
        v[i] = t; local += t;
    }
    s[tid] = local;
    if (tid == 0) sprefix = 0;
    __syncthreads();
    for (int off = 1; off < 512; off <<= 1) {
        int t = (tid >= off) ? s[tid - off] : 0;
        __syncthreads();
        s[tid] += t;
        __syncthreads();
    }
    if (tid == 0) atomicExch(&g_tot[b], s[511] + 1);
    if (tid < b) {
        int vt;
        do { vt = atomicAdd(&g_tot[tid], 0); } while (vt == 0);
        atomicAdd(&sprefix, vt - 1);
    }
    __syncthreads();
    int prefix = sprefix;

    int run = prefix + s[tid] - local;
#pragma unroll
    for (int i = 0; i < 4; i++) {
        int idx = base + i;
        if (idx < n) {
            g_rowptr[idx] = run;
            g_cur[idx]    = run;
            g_dinv[idx]   = rsqrtf((float)v[i] + 1.0f);
        }
        run += v[i];
    }
    if (b == 0 && tid == 0) g_rowptr[n] = e;
}

// ---------------- fill: int4-vectorized scatter of (src, dinv[src]) records --------
__global__ void k_fill(const int* __restrict__ src, const int* __restrict__ dst, int e) {
    int i = (blockIdx.x * blockDim.x + threadIdx.x) * 4;
    if (i + 3 < e) {
        int4 s4 = *(const int4*)(src + i);
        int4 d4 = *(const int4*)(dst + i);
        int p0 = atomicAdd(&g_cur[d4.x], 1);
        int p1 = atomicAdd(&g_cur[d4.y], 1);
        int p2 = atomicAdd(&g_cur[d4.z], 1);
        int p3 = atomicAdd(&g_cur[d4.w], 1);
        g_edge[p0] = make_uint2((unsigned)s4.x, __float_as_uint(g_dinv[s4.x]));
        g_edge[p1] = make_uint2((unsigned)s4.y, __float_as_uint(g_dinv[s4.y]));
        g_edge[p2] = make_uint2((unsigned)s4.z, __float_as_uint(g_dinv[s4.z]));
        g_edge[p3] = make_uint2((unsigned)s4.w, __float_as_uint(g_dinv[s4.w]));
    } else {
        for (; i < e; i++) {
            int s = src[i];
            int p = atomicAdd(&g_cur[dst[i]], 1);
            g_edge[p] = make_uint2((unsigned)s, __float_as_uint(g_dinv[s]));
        }
    }
}

// ---------------- agg1: warp per dst node, weighted fp16 gathers (MLP=8) -----------
// (R9-proven loop shape: simple uint2 edge loads, no uint4/peel)
__global__ void k_agg1(const float* __restrict__ b, int n) {
    int gidx = blockIdx.x * blockDim.x + threadIdx.x;
    int node = gidx >> 5;
    int lane = gidx & 31;
    if (node >= n) return;
    float di = g_dinv[node];

    uint2 v = *(const uint2*)(g_H1h + (size_t)node * C1 + 4 * lane);
    float2 p0 = __half22float2(*(__half2*)&v.x);
    float2 p1 = __half22float2(*(__half2*)&v.y);
    float a0 = di * p0.x, a1 = di * p0.y, a2 = di * p1.x, a3 = di * p1.y;

    int e   = g_rowptr[node];
    int end = g_rowptr[node + 1];
    for (; e + 7 < end; e += 8) {
        uint2 er[8], u[8];
#pragma unroll
        for (int j = 0; j < 8; j++) er[j] = g_edge[e + j];
#pragma unroll
        for (int j = 0; j < 8; j++)
            u[j] = *(const uint2*)(g_H1h + (size_t)er[j].x * C1 + 4 * lane);
#pragma unroll
        for (int j = 0; j < 8; j++) {
            float w = __uint_as_float(er[j].y);
            float2 q0 = __half22float2(*(__half2*)&u[j].x);
            float2 q1 = __half22float2(*(__half2*)&u[j].y);
            a0 += w * q0.x; a1 += w * q0.y;
            a2 += w * q1.x; a3 += w * q1.y;
        }
    }
    for (; e < end; e++) {
        uint2 e0 = g_edge[e];
        float w0 = __uint_as_float(e0.y);
        uint2 u0 = *(const uint2*)(g_H1h + (size_t)e0.x * C1 + 4 * lane);
        float2 q0 = __half22float2(*(__half2*)&u0.x);
        float2 q1 = __half22float2(*(__half2*)&u0.y);
        a0 += w0 * q0.x; a1 += w0 * q0.y;
        a2 += w0 * q1.x; a3 += w0 * q1.y;
    }
    float4 bb = *((const float4*)b + lane);
    uint2 o;
    *(__half2*)&o.x = __floats2half2_rn(fmaxf(di * a0 + bb.x, 0.f),
                                        fmaxf(di * a1 + bb.y, 0.f));
    *(__half2*)&o.y = __floats2half2_rn(fmaxf(di * a2 + bb.z, 0.f),
                                        fmaxf(di * a3 + bb.w, 0.f));
    *(uint2*)(g_A1h + (size_t)node * C1 + 4 * lane) = o;
}

// ---------------- GEMM2: H2h = fp16(A1 @ W2)  (FP16 MMA, K-tile 32) ----------------
__global__ __launch_bounds__(256) void k_gemm2(const float* __restrict__ W, int n) {
    __shared__ unsigned As[128 * 20];
    __shared__ unsigned Bs[16 * 72];

    int tid  = threadIdx.x;
    int wid  = tid >> 5;
    int lane = tid & 31;
    int g    = lane >> 2;
    int t    = lane & 3;
    int wm   = wid * 16;
    int rowBase = blockIdx.x * 128;

    float4 C[8];
#pragma unroll
    for (int b = 0; b < 8; b++) C[b] = make_float4(0.f, 0.f, 0.f, 0.f);

    for (int kt = 0; kt < 4; kt++) {
        int k0 = kt * 32;
#pragma unroll
        for (int i = tid; i < 2048; i += 256) {
            int r = i >> 4, ip = i & 15;
            int gr = rowBase + r;
            As[r * 20 + ip] = (gr < n)
                ? *(const unsigned*)&g_A1h[(size_t)gr * C1 + k0 + 2 * ip]
                : 0u;
        }
#pragma unroll
        for (int i = tid; i < 1024; i += 256) {
            int ii = i >> 6, c = i & 63;
            int gk = k0 + 2 * ii;
            Bs[ii * 72 + c] = h2_as_u(
                __floats2half2_rn(W[(size_t)gk * C2 + c], W[(size_t)(gk + 1) * C2 + c]));
        }
        __syncthreads();

#pragma unroll
        for (int ks = 0; ks < 2; ks++) {
            int kb = ks * 8;
            int r = wm + g;
            unsigned a0 = As[r * 20 + kb + t];
            unsigned a1 = As[(r + 8) * 20 + kb + t];
            unsigned a2 = As[r * 20 + kb + t + 4];
            unsigned a3 = As[(r + 8) * 20 + kb + t + 4];
#pragma unroll
            for (int nc = 0; nc < 8; nc++) {
                int cb = nc * 8 + g;
                unsigned b0 = Bs[(kb + t) * 72 + cb];
                unsigned b1 = Bs[(kb + t + 4) * 72 + cb];
                mma_f16(C[nc], a0, a1, a2, a3, b0, b1);
            }
        }
        __syncthreads();
    }

    int r = rowBase + wm + g;
#pragma unroll
    for (int nc = 0; nc < 8; nc++) {
        int c = nc * 8 + 2 * t;
        if (r < n)
            *(__half2*)&g_H2h[(size_t)r * C2 + c] = __floats2half2_rn(C[nc].x, C[nc].y);
        if (r + 8 < n)
            *(__half2*)&g_H2h[(size_t)(r + 8) * C2 + c] = __floats2half2_rn(C[nc].z, C[nc].w);
    }
}

// ---------------- agg2 (weighted fp16 gathers, MLP=8) + projection + resets --------
__global__ void k_agg2out(const float* __restrict__ b, const float* __restrict__ Wo,
                          const float* __restrict__ bo, float* __restrict__ out, int n) {
    int gidx = blockIdx.x * blockDim.x + threadIdx.x;
    int node = gidx >> 5;
    int lane = gidx & 31;
    if (gidx < 64) g_tot[gidx] = 0;              // reset lookback slots for next replay
    if (node >= n) return;
    float di = g_dinv[node];

    float2 p = __half22float2(*(const __half2*)(g_H2h + (size_t)node * C2 + 2 * lane));
    float a0 = di * p.x, a1 = di * p.y;

    int e   = g_rowptr[node];
    int end = g_rowptr[node + 1];
    for (; e + 7 < end; e += 8) {
        uint2 er[8];
        __half2 h[8];
#pragma unroll
        for (int j = 0; j < 8; j++) er[j] = g_edge[e + j];
#pragma unroll
        for (int j = 0; j < 8; j++)
            h[j] = *(const __half2*)(g_H2h + (size_t)er[j].x * C2 + 2 * lane);
#pragma unroll
        for (int j = 0; j < 8; j++) {
            float w  = __uint_as_float(er[j].y);
            float2 q = __half22float2(h[j]);
            a0 += w * q.x; a1 += w * q.y;
        }
    }
    for (; e < end; e++) {
        uint2 e0 = g_edge[e];
        float w0 = __uint_as_float(e0.y);
        float2 q = __half22float2(*(const __half2*)(g_H2h + (size_t)e0.x * C2 + 2 * lane));
        a0 += w0 * q.x; a1 += w0 * q.y;
    }
    float2 bb = *((const float2*)b + lane);
    float ox = fmaxf(di * a0 + bb.x, 0.f);
    float oy = fmaxf(di * a1 + bb.y, 0.f);

    int ch = 2 * lane;
    float d0 = ox * Wo[ch * 2]     + oy * Wo[(ch + 1) * 2];
    float d1 = ox * Wo[ch * 2 + 1] + oy * Wo[(ch + 1) * 2 + 1];
#pragma unroll
    for (int m = 16; m > 0; m >>= 1) {
        d0 += __shfl_xor_sync(0xFFFFFFFFu, d0, m);
        d1 += __shfl_xor_sync(0xFFFFFFFFu, d1, m);
    }
    if (lane == 0) {
        float2 r;
        r.x = d0 + bo[0];
        r.y = d1 + bo[1];
        ((float2*)out)[node] = r;
        g_cnt[node] = 0;            // re-zero histogram for the next graph replay
    }
}

// ---------------- launch ----------------
extern "C" void kernel_launch(void* const* d_in, const int* in_sizes, int n_in,
                              void* d_out, int out_size) {
    const float* x   = (const float*)d_in[0];
    const int*   ei  = (const int*)  d_in[1];
    const float* W1  = (const float*)d_in[2];
    const float* b1  = (const float*)d_in[3];
    const float* W2  = (const float*)d_in[4];
    const float* b2  = (const float*)d_in[5];
    const float* Wo  = (const float*)d_in[6];
    const float* bo  = (const float*)d_in[7];

    int n = in_sizes[0] / INC;
    int e = in_sizes[1] / 2;
    const int* src = ei;
    const int* dst = ei + e;

    k_head    <<<G1_BLOCKS + HIST_BLOCKS, 256>>>(x, W1, dst, n, e);
    k_scan    <<<NB_SCAN, 512>>>(n, e);
    k_fill    <<<(e / 4 + 255) / 256 + 1, 256>>>(src, dst, e);
    k_agg1    <<<(n * 32 + 255) / 256, 256>>>(b1, n);
    k_gemm2   <<<(n + 127) / 128, 256>>>(W2, n);
    k_agg2out <<<(n * 32 + 255) / 256, 256>>>(b2, Wo, bo, (float*)d_out, n);
}

// round 16
// speedup vs baseline: 1.0100x; 1.0100x over previous
#include <cuda_runtime.h>
#include <cuda_fp16.h>

#define NN      100000
#define EE      1600000
#define INC     165
#define C1      128
#define C2      64

#define G1_BLOCKS   782              // ceil(NN/128) gemm1 tiles
#define HIST_BLOCKS 1563             // ceil(EE/4/256) int4 histogram blocks
#define NB_SCAN     49               // ceil(NN/2048)

// ---------------- scratch (static device globals; no runtime alloc) ----------------
__device__ int    g_cnt[NN];         // zero-init at load; re-zeroed by k_agg2out
__device__ int    g_cur[NN];
__device__ int    g_rowptr[NN + 1];
__device__ int    g_tot[64];         // lookback totals (+1 sentinel); reset by k_agg2out
__device__ float  g_dinv[NN];
__device__ __align__(16) uint2 g_edge[EE];   // .x = src idx, .y = bits(dinv[src])
__device__ __half g_H1h[(size_t)NN * C1];    // raw fp16 X@W1
__device__ __half g_A1h[(size_t)NN * C1];    // relu layer-1 activations (fp16)
__device__ __half g_H2h[(size_t)NN * C2];    // raw fp16 A1@W2

// ---------------- helpers ----------------
__device__ __forceinline__ unsigned h2_as_u(__half2 h) {
    return *reinterpret_cast<unsigned*>(&h);
}

// fp16 MMA (m16n8k16, fp32 accum)
__device__ __forceinline__ void mma_f16(float4& c,
                                        unsigned a0, unsigned a1, unsigned a2, unsigned a3,
                                        unsigned b0, unsigned b1) {
    asm volatile(
        "mma.sync.aligned.m16n8k16.row.col.f32.f16.f16.f32 "
        "{%0,%1,%2,%3}, {%4,%5,%6,%7}, {%8,%9}, {%0,%1,%2,%3};"
        : "+f"(c.x), "+f"(c.y), "+f"(c.z), "+f"(c.w)
        : "r"(a0), "r"(a1), "r"(a2), "r"(a3), "r"(b0), "r"(b1));
}

// ---------------- k_head: gemm1 tiles (blocks < G1_BLOCKS) ∥ int4 histogram --------
__global__ __launch_bounds__(256) void k_head(const float* __restrict__ X,
                                              const float* __restrict__ W,
                                              const int* __restrict__ dst,
                                              int n, int e) {
    if (blockIdx.x >= G1_BLOCKS) {
        int i = (blockIdx.x - G1_BLOCKS) * 256 + threadIdx.x;
        int j = i * 4;
        if (j + 3 < e) {
            int4 d = *(const int4*)(dst + j);
            atomicAdd(&g_cnt[d.x], 1);
            atomicAdd(&g_cnt[d.y], 1);
            atomicAdd(&g_cnt[d.z], 1);
            atomicAdd(&g_cnt[d.w], 1);
        } else {
            for (; j < e; j++) atomicAdd(&g_cnt[dst[j]], 1);
        }
        return;
    }

    __shared__ unsigned As[128 * 20];   // [m][k/2] half2, stride 20 (16 used)
    __shared__ unsigned Bs[16 * 136];   // [k/2][n] half2 of (W[k],W[k+1]), stride 136

    int tid  = threadIdx.x;
    int wid  = tid >> 5;
    int lane = tid & 31;
    int g    = lane >> 2;
    int t    = lane & 3;
    int wm   = (wid & 3) * 32;
    int wn   = (wid >> 2) * 64;
    int rowBase = blockIdx.x * 128;

    float4 C[2][8];
#pragma unroll
    for (int a = 0; a < 2; a++)
#pragma unroll
        for (int b2 = 0; b2 < 8; b2++) C[a][b2] = make_float4(0.f, 0.f, 0.f, 0.f);

    for (int kt = 0; kt < 6; kt++) {        // 6*32 = 192 >= 165
        int k0 = kt * 32;
#pragma unroll
        for (int i = tid; i < 2048; i += 256) {
            int r = i >> 4, ip = i & 15;
            int gr = rowBase + r, gk = k0 + 2 * ip;
            float v0 = (gr < n && gk < INC)     ? X[(size_t)gr * INC + gk]     : 0.f;
            float v1 = (gr < n && gk + 1 < INC) ? X[(size_t)gr * INC + gk + 1] : 0.f;
            As[r * 20 + ip] = h2_as_u(__floats2half2_rn(v0, v1));
        }
#pragma unroll
        for (int i = tid; i < 2048; i += 256) {
            int ii = i >> 7, c = i & 127;
            int gk = k0 + 2 * ii;
            float v0 = (gk < INC)     ? W[(size_t)gk * C1 + c]       : 0.f;
            float v1 = (gk + 1 < INC) ? W[(size_t)(gk + 1) * C1 + c] : 0.f;
            Bs[ii * 136 + c] = h2_as_u(__floats2half2_rn(v0, v1));
        }
        __syncthreads();

#pragma unroll
        for (int ks = 0; ks < 2; ks++) {
            int kb = ks * 8;
            unsigned a[2][4];
#pragma unroll
            for (int mg = 0; mg < 2; mg++) {
                int r = wm + mg * 16 + g;
                a[mg][0] = As[r * 20 + kb + t];
                a[mg][1] = As[(r + 8) * 20 + kb + t];
                a[mg][2] = As[r * 20 + kb + t + 4];
                a[mg][3] = As[(r + 8) * 20 + kb + t + 4];
            }
#pragma unroll
            for (int nc = 0; nc < 8; nc++) {
                int cb = wn + nc * 8 + g;
                unsigned b0 = Bs[(kb + t) * 136 + cb];
                unsigned b1 = Bs[(kb + t + 4) * 136 + cb];
                mma_f16(C[0][nc], a[0][0], a[0][1], a[0][2], a[0][3], b0, b1);
                mma_f16(C[1][nc], a[1][0], a[1][1], a[1][2], a[1][3], b0, b1);
            }
        }
        __syncthreads();
    }

#pragma unroll
    for (int mg = 0; mg < 2; mg++) {
        int r = rowBase + wm + mg * 16 + g;
#pragma unroll
        for (int nc = 0; nc < 8; nc++) {
            int c = wn + nc * 8 + 2 * t;
            if (r < n)
                *(__half2*)&g_H1h[(size_t)r * C1 + c] =
                    __floats2half2_rn(C[mg][nc].x, C[mg][nc].y);
            if (r + 8 < n)
                *(__half2*)&g_H1h[(size_t)(r + 8) * C1 + c] =
                    __floats2half2_rn(C[mg][nc].z, C[mg][nc].w);
        }
    }
}

// ---------------- scan: fused block scan + parallel lookback + finalize ------------
__global__ void k_scan(int n, int e) {
    __shared__ int s[512];
    __shared__ int sprefix;
    int tid  = threadIdx.x;
    int b    = blockIdx.x;
    int base = b * 2048 + tid * 4;

    int v[4];
    int local = 0;
#pragma unroll
    for (int i = 0; i < 4; i++) {
        int idx = base + i;
        int t = (idx < n) ? g_cnt[idx] : 0;
        v[i] = t; local += t;
    }
    s[tid] = local;
    if (tid == 0) sprefix = 0;
    __syncthreads();
    for (int off = 1; off < 512; off <<= 1) {
        int t = (tid >= off) ? s[tid - off] : 0;
        __syncthreads();
        s[tid] += t;
        __syncthreads();
    }
    if (tid == 0) atomicExch(&g_tot[b], s[511] + 1);
    if (tid < b) {
        int vt;
        do { vt = atomicAdd(&g_tot[tid], 0); } while (vt == 0);
        atomicAdd(&sprefix, vt - 1);
    }
    __syncthreads();
    int prefix = sprefix;

    int run = prefix + s[tid] - local;
#pragma unroll
    for (int i = 0; i < 4; i++) {
        int idx = base + i;
        if (idx < n) {
            g_rowptr[idx] = run;
            g_cur[idx]    = run;
            g_dinv[idx]   = rsqrtf((float)v[i] + 1.0f);
        }
        run += v[i];
    }
    if (b == 0 && tid == 0) g_rowptr[n] = e;
}

// ---------------- fill: int4-vectorized scatter of (src, dinv[src]) records --------
__global__ void k_fill(const int* __restrict__ src, const int* __restrict__ dst, int e) {
    int i = (blockIdx.x * blockDim.x + threadIdx.x) * 4;
    if (i + 3 < e) {
        int4 s4 = *(const int4*)(src + i);
        int4 d4 = *(const int4*)(dst + i);
        int p0 = atomicAdd(&g_cur[d4.x], 1);
        int p1 = atomicAdd(&g_cur[d4.y], 1);
        int p2 = atomicAdd(&g_cur[d4.z], 1);
        int p3 = atomicAdd(&g_cur[d4.w], 1);
        g_edge[p0] = make_uint2((unsigned)s4.x, __float_as_uint(g_dinv[s4.x]));
        g_edge[p1] = make_uint2((unsigned)s4.y, __float_as_uint(g_dinv[s4.y]));
        g_edge[p2] = make_uint2((unsigned)s4.z, __float_as_uint(g_dinv[s4.z]));
        g_edge[p3] = make_uint2((unsigned)s4.w, __float_as_uint(g_dinv[s4.w]));
    } else {
        for (; i < e; i++) {
            int s = src[i];
            int p = atomicAdd(&g_cur[dst[i]], 1);
            g_edge[p] = make_uint2((unsigned)s, __float_as_uint(g_dinv[s]));
        }
    }
}

// ---------------- agg1: warp per dst node, weighted fp16 gathers (MLP=8) -----------
// (R9-proven loop shape: simple uint2 edge loads, no uint4/peel)
__global__ void k_agg1(const float* __restrict__ b, int n) {
    int gidx = blockIdx.x * blockDim.x + threadIdx.x;
    int node = gidx >> 5;
    int lane = gidx & 31;
    if (node >= n) return;
    float di = g_dinv[node];

    uint2 v = *(const uint2*)(g_H1h + (size_t)node * C1 + 4 * lane);
    float2 p0 = __half22float2(*(__half2*)&v.x);
    float2 p1 = __half22float2(*(__half2*)&v.y);
    float a0 = di * p0.x, a1 = di * p0.y, a2 = di * p1.x, a3 = di * p1.y;

    int e   = g_rowptr[node];
    int end = g_rowptr[node + 1];
    for (; e + 7 < end; e += 8) {
        uint2 er[8], u[8];
#pragma unroll
        for (int j = 0; j < 8; j++) er[j] = g_edge[e + j];
#pragma unroll
        for (int j = 0; j < 8; j++)
            u[j] = *(const uint2*)(g_H1h + (size_t)er[j].x * C1 + 4 * lane);
#pragma unroll
        for (int j = 0; j < 8; j++) {
            float w = __uint_as_float(er[j].y);
            float2 q0 = __half22float2(*(__half2*)&u[j].x);
            float2 q1 = __half22float2(*(__half2*)&u[j].y);
            a0 += w * q0.x; a1 += w * q0.y;
            a2 += w * q1.x; a3 += w * q1.y;
        }
    }
    for (; e < end; e++) {
        uint2 e0 = g_edge[e];
        float w0 = __uint_as_float(e0.y);
        uint2 u0 = *(const uint2*)(g_H1h + (size_t)e0.x * C1 + 4 * lane);
        float2 q0 = __half22float2(*(__half2*)&u0.x);
        float2 q1 = __half22float2(*(__half2*)&u0.y);
        a0 += w0 * q0.x; a1 += w0 * q0.y;
        a2 += w0 * q1.x; a3 += w0 * q1.y;
    }
    float4 bb = *((const float4*)b + lane);
    uint2 o;
    *(__half2*)&o.x = __floats2half2_rn(fmaxf(di * a0 + bb.x, 0.f),
                                        fmaxf(di * a1 + bb.y, 0.f));
    *(__half2*)&o.y = __floats2half2_rn(fmaxf(di * a2 + bb.z, 0.f),
                                        fmaxf(di * a3 + bb.w, 0.f));
    *(uint2*)(g_A1h + (size_t)node * C1 + 4 * lane) = o;
}

// ---------------- GEMM2: H2h = fp16(A1 @ W2)  (FP16 MMA, K-tile 32) ----------------
__global__ __launch_bounds__(256) void k_gemm2(const float* __restrict__ W, int n) {
    __shared__ unsigned As[128 * 20];
    __shared__ unsigned Bs[16 * 72];

    int tid  = threadIdx.x;
    int wid  = tid >> 5;
    int lane = tid & 31;
    int g    = lane >> 2;
    int t    = lane & 3;
    int wm   = wid * 16;
    int rowBase = blockIdx.x * 128;

    float4 C[8];
#pragma unroll
    for (int b = 0; b < 8; b++) C[b] = make_float4(0.f, 0.f, 0.f, 0.f);

    for (int kt = 0; kt < 4; kt++) {
        int k0 = kt * 32;
#pragma unroll
        for (int i = tid; i < 2048; i += 256) {
            int r = i >> 4, ip = i & 15;
            int gr = rowBase + r;
            As[r * 20 + ip] = (gr < n)
                ? *(const unsigned*)&g_A1h[(size_t)gr * C1 + k0 + 2 * ip]
                : 0u;
        }
#pragma unroll
        for (int i = tid; i < 1024; i += 256) {
            int ii = i >> 6, c = i & 63;
            int gk = k0 + 2 * ii;
            Bs[ii * 72 + c] = h2_as_u(
                __floats2half2_rn(W[(size_t)gk * C2 + c], W[(size_t)(gk + 1) * C2 + c]));
        }
        __syncthreads();

#pragma unroll
        for (int ks = 0; ks < 2; ks++) {
            int kb = ks * 8;
            int r = wm + g;
            unsigned a0 = As[r * 20 + kb + t];
            unsigned a1 = As[(r + 8) * 20 + kb + t];
            unsigned a2 = As[r * 20 + kb + t + 4];
            unsigned a3 = As[(r + 8) * 20 + kb + t + 4];
#pragma unroll
            for (int nc = 0; nc < 8; nc++) {
                int cb = nc * 8 + g;
                unsigned b0 = Bs[(kb + t) * 72 + cb];
                unsigned b1 = Bs[(kb + t + 4) * 72 + cb];
                mma_f16(C[nc], a0, a1, a2, a3, b0, b1);
            }
        }
        __syncthreads();
    }

    int r = rowBase + wm + g;
#pragma unroll
    for (int nc = 0; nc < 8; nc++) {
        int c = nc * 8 + 2 * t;
        if (r < n)
            *(__half2*)&g_H2h[(size_t)r * C2 + c] = __floats2half2_rn(C[nc].x, C[nc].y);
        if (r + 8 < n)
            *(__half2*)&g_H2h[(size_t)(r + 8) * C2 + c] = __floats2half2_rn(C[nc].z, C[nc].w);
    }
}

// ---------------- agg2 (weighted fp16 gathers, MLP=8) + projection + resets --------
__global__ void k_agg2out(const float* __restrict__ b, const float* __restrict__ Wo,
                          const float* __restrict__ bo, float* __restrict__ out, int n) {
    int gidx = blockIdx.x * blockDim.x + threadIdx.x;
    int node = gidx >> 5;
    int lane = gidx & 31;
    if (gidx < 64) g_tot[gidx] = 0;              // reset lookback slots for next replay
    if (node >= n) return;
    float di = g_dinv[node];

    float2 p = __half22float2(*(const __half2*)(g_H2h + (size_t)node * C2 + 2 * lane));
    float a0 = di * p.x, a1 = di * p.y;

    int e   = g_rowptr[node];
    int end = g_rowptr[node + 1];
    for (; e + 7 < end; e += 8) {
        uint2 er[8];
        __half2 h[8];
#pragma unroll
        for (int j = 0; j < 8; j++) er[j] = g_edge[e + j];
#pragma unroll
        for (int j = 0; j < 8; j++)
            h[j] = *(const __half2*)(g_H2h + (size_t)er[j].x * C2 + 2 * lane);
#pragma unroll
        for (int j = 0; j < 8; j++) {
            float w  = __uint_as_float(er[j].y);
            float2 q = __half22float2(h[j]);
            a0 += w * q.x; a1 += w * q.y;
        }
    }
    for (; e < end; e++) {
        uint2 e0 = g_edge[e];
        float w0 = __uint_as_float(e0.y);
        float2 q = __half22float2(*(const __half2*)(g_H2h + (size_t)e0.x * C2 + 2 * lane));
        a0 += w0 * q.x; a1 += w0 * q.y;
    }
    float2 bb = *((const float2*)b + lane);
    float ox = fmaxf(di * a0 + bb.x, 0.f);
    float oy = fmaxf(di * a1 + bb.y, 0.f);

    int ch = 2 * lane;
    float d0 = ox * Wo[ch * 2]     + oy * Wo[(ch + 1) * 2];
    float d1 = ox * Wo[ch * 2 + 1] + oy * Wo[(ch + 1) * 2 + 1];
#pragma unroll
    for (int m = 16; m > 0; m >>= 1) {
        d0 += __shfl_xor_sync(0xFFFFFFFFu, d0, m);
        d1 += __shfl_xor_sync(0xFFFFFFFFu, d1, m);
    }
    if (lane == 0) {
        float2 r;
        r.x = d0 + bo[0];
        r.y = d1 + bo[1];
        ((float2*)out)[node] = r;
        g_cnt[node] = 0;            // re-zero histogram for the next graph replay
    }
}

// ---------------- launch ----------------
extern "C" void kernel_launch(void* const* d_in, const int* in_sizes, int n_in,
                              void* d_out, int out_size) {
    const float* x   = (const float*)d_in[0];
    const int*   ei  = (const int*)  d_in[1];
    const float* W1  = (const float*)d_in[2];
    const float* b1  = (const float*)d_in[3];
    const float* W2  = (const float*)d_in[4];
    const float* b2  = (const float*)d_in[5];
    const float* Wo  = (const float*)d_in[6];
    const float* bo  = (const float*)d_in[7];

    int n = in_sizes[0] / INC;
    int e = in_sizes[1] / 2;
    const int* src = ei;
    const int* dst = ei + e;

    k_head    <<<G1_BLOCKS + HIST_BLOCKS, 256>>>(x, W1, dst, n, e);
    k_scan    <<<NB_SCAN, 512>>>(n, e);
    k_fill    <<<(e / 4 + 255) / 256 + 1, 256>>>(src, dst, e);
    k_agg1    <<<(n * 32 + 255) / 256, 256>>>(b1, n);
    k_gemm2   <<<(n + 127) / 128, 256>>>(W2, n);
    k_agg2out <<<(n * 32 + 255) / 256, 256>>>(b2, Wo, bo, (float*)d_out, n);
}

// round 17
// speedup vs baseline: 1.0328x; 1.0226x over previous
#include <cuda_runtime.h>
#include <cuda_fp16.h>

#define NN      100000
#define EE      1600000
#define INC     165
#define C1      128
#define C2      64

#define G1_BLOCKS    782             // ceil(NN/128) gemm1 tiles
#define HIST_BLOCKS  1563            // ceil(EE/4/256) int4 histogram blocks
#define NB_SCAN      49              // ceil(NN/2048)
#define FILL_BLOCKS  1564            // ceil(EE/4/256)+1 fill blocks
#define SCALE_BLOCKS 6250            // NN*C1/8 uint4 items / 256

// ---------------- scratch (static device globals; no runtime alloc) ----------------
__device__ int    g_cnt[NN];         // zero-init at load; re-zeroed by k_agg2out
__device__ int    g_cur[NN];
__device__ int    g_rowptr[NN + 1];
__device__ int    g_tot[64];         // lookback totals (+1 sentinel); reset by k_agg2out
__device__ float  g_dinv[NN];
__device__ int    g_ecol[EE];        // 4B edge record: src index only
__device__ __align__(16) __half g_H1h[(size_t)NN * C1];  // X@W1, then scaled by dinv[row]
__device__ __align__(16) __half g_A1h[(size_t)NN * C1];  // relu layer-1 activations
__device__ __align__(16) __half g_H2h[(size_t)NN * C2];  // dinv[row] * (A1@W2)

// ---------------- helpers ----------------
__device__ __forceinline__ unsigned h2_as_u(__half2 h) {
    return *reinterpret_cast<unsigned*>(&h);
}

// fp16 MMA (m16n8k16, fp32 accum)
__device__ __forceinline__ void mma_f16(float4& c,
                                        unsigned a0, unsigned a1, unsigned a2, unsigned a3,
                                        unsigned b0, unsigned b1) {
    asm volatile(
        "mma.sync.aligned.m16n8k16.row.col.f32.f16.f16.f32 "
        "{%0,%1,%2,%3}, {%4,%5,%6,%7}, {%8,%9}, {%0,%1,%2,%3};"
        : "+f"(c.x), "+f"(c.y), "+f"(c.z), "+f"(c.w)
        : "r"(a0), "r"(a1), "r"(a2), "r"(a3), "r"(b0), "r"(b1));
}

// ---------------- k_head: gemm1 tiles (blocks < G1_BLOCKS) ∥ int4 histogram --------
__global__ __launch_bounds__(256) void k_head(const float* __restrict__ X,
                                              const float* __restrict__ W,
                                              const int* __restrict__ dst,
                                              int n, int e) {
    if (blockIdx.x >= G1_BLOCKS) {
        int i = (blockIdx.x - G1_BLOCKS) * 256 + threadIdx.x;
        int j = i * 4;
        if (j + 3 < e) {
            int4 d = *(const int4*)(dst + j);
            atomicAdd(&g_cnt[d.x], 1);
            atomicAdd(&g_cnt[d.y], 1);
            atomicAdd(&g_cnt[d.z], 1);
            atomicAdd(&g_cnt[d.w], 1);
        } else {
            for (; j < e; j++) atomicAdd(&g_cnt[dst[j]], 1);
        }
        return;
    }

    __shared__ unsigned As[128 * 20];   // [m][k/2] half2, stride 20 (16 used)
    __shared__ unsigned Bs[16 * 136];   // [k/2][n] half2 of (W[k],W[k+1]), stride 136

    int tid  = threadIdx.x;
    int wid  = tid >> 5;
    int lane = tid & 31;
    int g    = lane >> 2;
    int t    = lane & 3;
    int wm   = (wid & 3) * 32;
    int wn   = (wid >> 2) * 64;
    int rowBase = blockIdx.x * 128;

    float4 C[2][8];
#pragma unroll
    for (int a = 0; a < 2; a++)
#pragma unroll
        for (int b2 = 0; b2 < 8; b2++) C[a][b2] = make_float4(0.f, 0.f, 0.f, 0.f);

    for (int kt = 0; kt < 6; kt++) {        // 6*32 = 192 >= 165
        int k0 = kt * 32;
#pragma unroll
        for (int i = tid; i < 2048; i += 256) {
            int r = i >> 4, ip = i & 15;
            int gr = rowBase + r, gk = k0 + 2 * ip;
            float v0 = (gr < n && gk < INC)     ? X[(size_t)gr * INC + gk]     : 0.f;
            float v1 = (gr < n && gk + 1 < INC) ? X[(size_t)gr * INC + gk + 1] : 0.f;
            As[r * 20 + ip] = h2_as_u(__floats2half2_rn(v0, v1));
        }
#pragma unroll
        for (int i = tid; i < 2048; i += 256) {
            int ii = i >> 7, c = i & 127;
            int gk = k0 + 2 * ii;
            float v0 = (gk < INC)     ? W[(size_t)gk * C1 + c]       : 0.f;
            float v1 = (gk + 1 < INC) ? W[(size_t)(gk + 1) * C1 + c] : 0.f;
            Bs[ii * 136 + c] = h2_as_u(__floats2half2_rn(v0, v1));
        }
        __syncthreads();

#pragma unroll
        for (int ks = 0; ks < 2; ks++) {
            int kb = ks * 8;
            unsigned a[2][4];
#pragma unroll
            for (int mg = 0; mg < 2; mg++) {
                int r = wm + mg * 16 + g;
                a[mg][0] = As[r * 20 + kb + t];
                a[mg][1] = As[(r + 8) * 20 + kb + t];
                a[mg][2] = As[r * 20 + kb + t + 4];
                a[mg][3] = As[(r + 8) * 20 + kb + t + 4];
            }
#pragma unroll
            for (int nc = 0; nc < 8; nc++) {
                int cb = wn + nc * 8 + g;
                unsigned b0 = Bs[(kb + t) * 136 + cb];
                unsigned b1 = Bs[(kb + t + 4) * 136 + cb];
                mma_f16(C[0][nc], a[0][0], a[0][1], a[0][2], a[0][3], b0, b1);
                mma_f16(C[1][nc], a[1][0], a[1][1], a[1][2], a[1][3], b0, b1);
            }
        }
        __syncthreads();
    }

#pragma unroll
    for (int mg = 0; mg < 2; mg++) {
        int r = rowBase + wm + mg * 16 + g;
#pragma unroll
        for (int nc = 0; nc < 8; nc++) {
            int c = wn + nc * 8 + 2 * t;
            if (r < n)
                *(__half2*)&g_H1h[(size_t)r * C1 + c] =
                    __floats2half2_rn(C[mg][nc].x, C[mg][nc].y);
            if (r + 8 < n)
                *(__half2*)&g_H1h[(size_t)(r + 8) * C1 + c] =
                    __floats2half2_rn(C[mg][nc].z, C[mg][nc].w);
        }
    }
}

// ---------------- scan: fused block scan + parallel lookback + finalize ------------
__global__ void k_scan(int n, int e) {
    __shared__ int s[512];
    __shared__ int sprefix;
    int tid  = threadIdx.x;
    int b    = blockIdx.x;
    int base = b * 2048 + tid * 4;

    int v[4];
    int local = 0;
#pragma unroll
    for (int i = 0; i < 4; i++) {
        int idx = base + i;
        int t = (idx < n) ? g_cnt[idx] : 0;
        v[i] = t; local += t;
    }
    s[tid] = local;
    if (tid == 0) sprefix = 0;
    __syncthreads();
    for (int off = 1; off < 512; off <<= 1) {
        int t = (tid >= off) ? s[tid - off] : 0;
        __syncthreads();
        s[tid] += t;
        __syncthreads();
    }
    if (tid == 0) atomicExch(&g_tot[b], s[511] + 1);
    if (tid < b) {
        int vt;
        do { vt = atomicAdd(&g_tot[tid], 0); } while (vt == 0);
        atomicAdd(&sprefix, vt - 1);
    }
    __syncthreads();
    int prefix = sprefix;

    int run = prefix + s[tid] - local;
#pragma unroll
    for (int i = 0; i < 4; i++) {
        int idx = base + i;
        if (idx < n) {
            g_rowptr[idx] = run;
            g_cur[idx]    = run;
            g_dinv[idx]   = rsqrtf((float)v[i] + 1.0f);
        }
        run += v[i];
    }
    if (b == 0 && tid == 0) g_rowptr[n] = e;
}

// ---------------- fillscale: CSR fill (src-only records) ∥ H1h *= dinv[row] --------
__global__ void k_fillscale(const int* __restrict__ src, const int* __restrict__ dst,
                            int e, int n) {
    if (blockIdx.x < FILL_BLOCKS) {
        // ---- fill branch: int4 reads, 4B scatter, no dinv gather ----
        int i = (blockIdx.x * 256 + threadIdx.x) * 4;
        if (i + 3 < e) {
            int4 s4 = *(const int4*)(src + i);
            int4 d4 = *(const int4*)(dst + i);
            int p0 = atomicAdd(&g_cur[d4.x], 1);
            int p1 = atomicAdd(&g_cur[d4.y], 1);
            int p2 = atomicAdd(&g_cur[d4.z], 1);
            int p3 = atomicAdd(&g_cur[d4.w], 1);
            g_ecol[p0] = s4.x;
            g_ecol[p1] = s4.y;
            g_ecol[p2] = s4.z;
            g_ecol[p3] = s4.w;
        } else {
            for (; i < e; i++) {
                int p = atomicAdd(&g_cur[dst[i]], 1);
                g_ecol[p] = src[i];
            }
        }
        return;
    }
    // ---- scale branch: H1h[row][*] *= dinv[row]  (uint4 = 8 halves per thread) ----
    long idx = (long)(blockIdx.x - FILL_BLOCKS) * 256 + threadIdx.x;
    long total = (long)n * C1 / 8;
    if (idx < total) {
        int row = (int)(idx >> 4);                 // 16 uint4 per row
        __half2 d2 = __float2half2_rn(g_dinv[row]);
        uint4* ptr = (uint4*)g_H1h + idx;
        uint4 v = *ptr;
        __half2* h = (__half2*)&v;
        h[0] = __hmul2(h[0], d2);
        h[1] = __hmul2(h[1], d2);
        h[2] = __hmul2(h[2], d2);
        h[3] = __hmul2(h[3], d2);
        *ptr = v;
    }
}

// ---------------- agg1: warp per dst node, weightless fp16 gathers (MLP=8) ---------
__global__ void k_agg1(const float* __restrict__ b, int n) {
    int gidx = blockIdx.x * blockDim.x + threadIdx.x;
    int node = gidx >> 5;
    int lane = gidx & 31;
    if (node >= n) return;
    float di = g_dinv[node];

    uint2 v = *(const uint2*)(g_H1h + (size_t)node * C1 + 4 * lane);
    float2 p0 = __half22float2(*(__half2*)&v.x);
    float2 p1 = __half22float2(*(__half2*)&v.y);
    float a0 = p0.x, a1 = p0.y, a2 = p1.x, a3 = p1.y;   // self term (pre-scaled)

    int e   = g_rowptr[node];
    int end = g_rowptr[node + 1];
    for (; e + 7 < end; e += 8) {
        int sidx[8];
        uint2 u[8];
#pragma unroll
        for (int j = 0; j < 8; j++) sidx[j] = g_ecol[e + j];
#pragma unroll
        for (int j = 0; j < 8; j++)
            u[j] = *(const uint2*)(g_H1h + (size_t)sidx[j] * C1 + 4 * lane);
#pragma unroll
        for (int j = 0; j < 8; j++) {
            float2 q0 = __half22float2(*(__half2*)&u[j].x);
            float2 q1 = __half22float2(*(__half2*)&u[j].y);
            a0 += q0.x; a1 += q0.y; a2 += q1.x; a3 += q1.y;
        }
    }
    for (; e < end; e++) {
        int s0 = g_ecol[e];
        uint2 u0 = *(const uint2*)(g_H1h + (size_t)s0 * C1 + 4 * lane);
        float2 q0 = __half22float2(*(__half2*)&u0.x);
        float2 q1 = __half22float2(*(__half2*)&u0.y);
        a0 += q0.x; a1 += q0.y; a2 += q1.x; a3 += q1.y;
    }
    float4 bb = *((const float4*)b + lane);
    uint2 o;
    *(__half2*)&o.x = __floats2half2_rn(fmaxf(di * a0 + bb.x, 0.f),
                                        fmaxf(di * a1 + bb.y, 0.f));
    *(__half2*)&o.y = __floats2half2_rn(fmaxf(di * a2 + bb.z, 0.f),
                                        fmaxf(di * a3 + bb.w, 0.f));
    *(uint2*)(g_A1h + (size_t)node * C1 + 4 * lane) = o;
}

// ---------------- GEMM2: H2h = fp16(dinv[r] * (A1 @ W2))  (FP16 MMA) ---------------
__global__ __launch_bounds__(256) void k_gemm2(const float* __restrict__ W, int n) {
    __shared__ unsigned As[128 * 20];
    __shared__ unsigned Bs[16 * 72];

    int tid  = threadIdx.x;
    int wid  = tid >> 5;
    int lane = tid & 31;
    int g    = lane >> 2;
    int t    = lane & 3;
    int wm   = wid * 16;
    int rowBase = blockIdx.x * 128;

    float4 C[8];
#pragma unroll
    for (int b = 0; b < 8; b++) C[b] = make_float4(0.f, 0.f, 0.f, 0.f);

    for (int kt = 0; kt < 4; kt++) {
        int k0 = kt * 32;
#pragma unroll
        for (int i = tid; i < 2048; i += 256) {
            int r = i >> 4, ip = i & 15;
            int gr = rowBase + r;
            As[r * 20 + ip] = (gr < n)
                ? *(const unsigned*)&g_A1h[(size_t)gr * C1 + k0 + 2 * ip]
                : 0u;
        }
#pragma unroll
        for (int i = tid; i < 1024; i += 256) {
            int ii = i >> 6, c = i & 63;
            int gk = k0 + 2 * ii;
            Bs[ii * 72 + c] = h2_as_u(
                __floats2half2_rn(W[(size_t)gk * C2 + c], W[(size_t)(gk + 1) * C2 + c]));
        }
        __syncthreads();

#pragma unroll
        for (int ks = 0; ks < 2; ks++) {
            int kb = ks * 8;
            int r = wm + g;
            unsigned a0 = As[r * 20 + kb + t];
            unsigned a1 = As[(r + 8) * 20 + kb + t];
            unsigned a2 = As[r * 20 + kb + t + 4];
            unsigned a3 = As[(r + 8) * 20 + kb + t + 4];
#pragma unroll
            for (int nc = 0; nc < 8; nc++) {
                int cb = nc * 8 + g;
                unsigned b0 = Bs[(kb + t) * 72 + cb];
                unsigned b1 = Bs[(kb + t + 4) * 72 + cb];
                mma_f16(C[nc], a0, a1, a2, a3, b0, b1);
            }
        }
        __syncthreads();
    }

    int r = rowBase + wm + g;
    float dv0 = (r < n)     ? g_dinv[r]     : 0.f;
    float dv1 = (r + 8 < n) ? g_dinv[r + 8] : 0.f;
#pragma unroll
    for (int nc = 0; nc < 8; nc++) {
        int c = nc * 8 + 2 * t;
        if (r < n)
            *(__half2*)&g_H2h[(size_t)r * C2 + c] =
                __floats2half2_rn(dv0 * C[nc].x, dv0 * C[nc].y);
        if (r + 8 < n)
            *(__half2*)&g_H2h[(size_t)(r + 8) * C2 + c] =
                __floats2half2_rn(dv1 * C[nc].z, dv1 * C[nc].w);
    }
}

// ---------------- agg2 (weightless fp16 gathers) + output projection + resets ------
__global__ void k_agg2out(const float* __restrict__ b, const float* __restrict__ Wo,
                          const float* __restrict__ bo, float* __restrict__ out, int n) {
    int gidx = blockIdx.x * blockDim.x + threadIdx.x;
    int node = gidx >> 5;
    int lane = gidx & 31;
    if (gidx < 64) g_tot[gidx] = 0;              // reset lookback slots for next replay
    if (node >= n) return;
    float di = g_dinv[node];

    float2 p = __half22float2(*(const __half2*)(g_H2h + (size_t)node * C2 + 2 * lane));
    float a0 = p.x, a1 = p.y;                    // self term (pre-scaled)

    int e   = g_rowptr[node];
    int end = g_rowptr[node + 1];
    for (; e + 7 < end; e += 8) {
        int sidx[8];
        __half2 h[8];
#pragma unroll
        for (int j = 0; j < 8; j++) sidx[j] = g_ecol[e + j];
#pragma unroll
        for (int j = 0; j < 8; j++)
            h[j] = *(const __half2*)(g_H2h + (size_t)sidx[j] * C2 + 2 * lane);
#pragma unroll
        for (int j = 0; j < 8; j++) {
            float2 q = __half22float2(h[j]);
            a0 += q.x; a1 += q.y;
        }
    }
    for (; e < end; e++) {
        int s0 = g_ecol[e];
        float2 q = __half22float2(*(const __half2*)(g_H2h + (size_t)s0 * C2 + 2 * lane));
        a0 += q.x; a1 += q.y;
    }
    float2 bb = *((const float2*)b + lane);
    float ox = fmaxf(di * a0 + bb.x, 0.f);
    float oy = fmaxf(di * a1 + bb.y, 0.f);

    int ch = 2 * lane;
    float d0 = ox * Wo[ch * 2]     + oy * Wo[(ch + 1) * 2];
    float d1 = ox * Wo[ch * 2 + 1] + oy * Wo[(ch + 1) * 2 + 1];
#pragma unroll
    for (int m = 16; m > 0; m >>= 1) {
        d0 += __shfl_xor_sync(0xFFFFFFFFu, d0, m);
        d1 += __shfl_xor_sync(0xFFFFFFFFu, d1, m);
    }
    if (lane == 0) {
        float2 r;
        r.x = d0 + bo[0];
        r.y = d1 + bo[1];
        ((float2*)out)[node] = r;
        g_cnt[node] = 0;            // re-zero histogram for the next graph replay
    }
}

// ---------------- launch ----------------
extern "C" void kernel_launch(void* const* d_in, const int* in_sizes, int n_in,
                              void* d_out, int out_size) {
    const float* x   = (const float*)d_in[0];
    const int*   ei  = (const int*)  d_in[1];
    const float* W1  = (const float*)d_in[2];
    const float* b1  = (const float*)d_in[3];
    const float* W2  = (const float*)d_in[4];
    const float* b2  = (const float*)d_in[5];
    const float* Wo  = (const float*)d_in[6];
    const float* bo  = (const float*)d_in[7];

    int n = in_sizes[0] / INC;
    int e = in_sizes[1] / 2;
    const int* src = ei;
    const int* dst = ei + e;

    k_head     <<<G1_BLOCKS + HIST_BLOCKS, 256>>>(x, W1, dst, n, e);
    k_scan     <<<NB_SCAN, 512>>>(n, e);
    k_fillscale<<<FILL_BLOCKS + SCALE_BLOCKS, 256>>>(src, dst, e, n);
    k_agg1     <<<(n * 32 + 255) / 256, 256>>>(b1, n);
    k_gemm2    <<<(n + 127) / 128, 256>>>(W2, n);
    k_agg2out  <<<(n * 32 + 255) / 256, 256>>>(b2, Wo, bo, (float*)d_out, n);
}